// round 6
// baseline (speedup 1.0000x reference)
#include <cuda_runtime.h>
#include <cuda_bf16.h>
#include <math.h>

#define N_NODES    100000
#define N_EDGES    1600000
#define HIDDEN     64
#define NUM_GRAPHS 512

// Scratch (no allocations -> __device__ globals)
__device__ float g_p[N_NODES];            // x . W_rel
__device__ float g_score[N_NODES];        // x . W_root + b_rel + sum_edges p[src]
__device__ int   g_start[NUM_GRAPHS + 1]; // per-graph node range starts

// ---- inline dtype sniff: odd int32 words of edge buffer are all 0 iff int64 ----
__device__ __forceinline__ int sniff_is64(const int* __restrict__ ei32) {
    int a = ei32[1], b = ei32[3], c = ei32[5], d = ei32[7];  // L1-resident
    return ((a | b) | (c | d)) == 0;
}

__device__ __forceinline__ int load_idx(const void* p, long long i, int is64) {
    if (is64) return (int)((const long long*)p)[i];
    return ((const int*)p)[i];
}

// ---------- K1: fused node dots + graph bounds ----------
// Dots: 1 thread = 1 node; 16 unrolled float4 loads, no shuffles.
#define DOTS_BLOCKS   ((N_NODES + 255) / 256)               // 391
#define BOUNDS_BLOCKS ((N_NODES + 4 * 256 - 1) / (4 * 256)) // 98
__global__ __launch_bounds__(256)
void k1_dots_bounds(const float* __restrict__ x,
                    const float* __restrict__ W_rel,
                    const float* __restrict__ b_rel,
                    const float* __restrict__ W_root,
                    const void*  __restrict__ batch,
                    const int*   __restrict__ ei32) {
    if (blockIdx.x < DOTS_BLOCKS) {
        int node = blockIdx.x * 256 + threadIdx.x;
        if (node >= N_NODES) return;
        const float4* row = (const float4*)(x + (size_t)node * HIDDEN);
        const float4* wr4 = (const float4*)W_rel;
        const float4* wo4 = (const float4*)W_root;
        float sr = 0.0f, so = 0.0f;
        #pragma unroll
        for (int j = 0; j < 16; ++j) {
            float4 v = row[j];                 // 16 independent loads in flight
            float4 a = __ldg(wr4 + j);         // warp-uniform broadcast, L1-hit
            float4 c = __ldg(wo4 + j);
            sr += v.x * a.x + v.y * a.y + v.z * a.z + v.w * a.w;
            so += v.x * c.x + v.y * c.y + v.z * c.z + v.w * c.w;
        }
        g_p[node]     = sr;
        g_score[node] = so + __ldg(&b_rel[0]);
    } else {
        // ---- graph bounds (batch is sorted) ----
        int is64 = sniff_is64(ei32);
        int t  = (blockIdx.x - DOTS_BLOCKS) * blockDim.x + threadIdx.x;
        int i0 = t * 4;
        if (i0 >= N_NODES) return;
        int b0, b1, b2, b3, prev;
        if (!is64 && i0 + 4 <= N_NODES) {
            int4 v = ((const int4*)batch)[t];
            b0 = v.x; b1 = v.y; b2 = v.z; b3 = v.w;
            prev = (i0 == 0) ? -1 : ((const int*)batch)[i0 - 1];
        } else {
            b0 = (i0     < N_NODES) ? load_idx(batch, i0,     is64) : -2;
            b1 = (i0 + 1 < N_NODES) ? load_idx(batch, i0 + 1, is64) : -2;
            b2 = (i0 + 2 < N_NODES) ? load_idx(batch, i0 + 2, is64) : -2;
            b3 = (i0 + 3 < N_NODES) ? load_idx(batch, i0 + 3, is64) : -2;
            prev = (i0 == 0) ? -1 : load_idx(batch, i0 - 1, is64);
        }
        int bs[4] = {b0, b1, b2, b3};
        #pragma unroll
        for (int j = 0; j < 4; ++j) {
            int i = i0 + j;
            if (i >= N_NODES) break;
            int b = bs[j];
            for (int g = prev + 1; g <= b; ++g) g_start[g] = i;
            if (i == N_NODES - 1)
                for (int g = b + 1; g <= NUM_GRAPHS; ++g) g_start[g] = N_NODES;
            prev = b;
        }
    }
}

// ---------- K2: edge scatter, 8 edges/thread (at L2 atomic sector floor) ----------
#define EPT 8
__global__ void k_edges(const void* __restrict__ edge_index) {
    int t  = blockIdx.x * blockDim.x + threadIdx.x;
    long long e0 = (long long)t * EPT;
    if (e0 >= N_EDGES) return;
    int is64 = sniff_is64((const int*)edge_index);
    if (!is64) {
        const int4* src4 = (const int4*)edge_index;
        const int4* dst4 = (const int4*)((const int*)edge_index + N_EDGES);
        int4 sa = src4[2 * t];
        int4 sb = src4[2 * t + 1];
        int4 da = dst4[2 * t];
        int4 db = dst4[2 * t + 1];
        float p0 = __ldg(&g_p[sa.x]);
        float p1 = __ldg(&g_p[sa.y]);
        float p2 = __ldg(&g_p[sa.z]);
        float p3 = __ldg(&g_p[sa.w]);
        float p4 = __ldg(&g_p[sb.x]);
        float p5 = __ldg(&g_p[sb.y]);
        float p6 = __ldg(&g_p[sb.z]);
        float p7 = __ldg(&g_p[sb.w]);
        atomicAdd(&g_score[da.x], p0);
        atomicAdd(&g_score[da.y], p1);
        atomicAdd(&g_score[da.z], p2);
        atomicAdd(&g_score[da.w], p3);
        atomicAdd(&g_score[db.x], p4);
        atomicAdd(&g_score[db.y], p5);
        atomicAdd(&g_score[db.z], p6);
        atomicAdd(&g_score[db.w], p7);
    } else {
        #pragma unroll
        for (int k = 0; k < EPT; ++k) {
            long long e = e0 + k;
            if (e < N_EDGES) {
                int s = load_idx(edge_index, e, 1);
                int d = load_idx(edge_index, (long long)N_EDGES + e, 1);
                atomicAdd(&g_score[d], g_p[s]);
            }
        }
    }
}

// ---------- K3: fused per-graph online softmax + weighted pooling ----------
__global__ __launch_bounds__(256, 4)
void k_pool(const float* __restrict__ x, float* __restrict__ out) {
    __shared__ float red_m[256];
    __shared__ float red_z[256];
    __shared__ float s_m, s_rz;
    __shared__ __align__(16) float4 red4[16 * 16];  // phase-C partials [16 groups][16 float4]
    int g   = blockIdx.x;
    int tid = threadIdx.x;
    int s   = g_start[g];
    int e   = g_start[g + 1];

    // Phase A: online (max, sum-exp) in one pass. -1e30 sentinel avoids inf-inf NaN.
    float m = -1e30f, z = 0.0f;
    for (int i = s + tid; i < e; i += 256) {
        float sc = g_score[i];
        float nm = fmaxf(m, sc);
        z = z * __expf(m - nm) + __expf(sc - nm);
        m = nm;
    }
    red_m[tid] = m; red_z[tid] = z;
    __syncthreads();
    #pragma unroll
    for (int off = 128; off > 0; off >>= 1) {
        if (tid < off) {
            float ma = red_m[tid],       za = red_z[tid];
            float mb = red_m[tid + off], zb = red_z[tid + off];
            float nm = fmaxf(ma, mb);
            red_m[tid] = nm;
            red_z[tid] = za * __expf(ma - nm) + zb * __expf(mb - nm);
        }
        __syncthreads();
    }
    if (tid == 0) {
        s_m  = red_m[0];
        s_rz = (e > s && red_z[0] > 0.0f) ? (1.0f / red_z[0]) : 0.0f;
    }
    __syncthreads();
    m = s_m;
    float rz = s_rz;

    // Phase C: 16 groups of 16 threads; group handles rows s+grp, s+grp+16, ...
    // Each thread owns one float4 chunk of the 64-wide row.
    int q   = tid & 15;         // float4 index within row
    int grp = tid >> 4;         // 16 groups
    float4 acc = make_float4(0.f, 0.f, 0.f, 0.f);
    const float4* x4 = (const float4*)x;
    for (int i = s + grp; i < e; i += 16) {
        float w = __expf(g_score[i] - m);    // broadcast within group
        float4 v = x4[(size_t)i * 16 + q];
        acc.x += v.x * w; acc.y += v.y * w; acc.z += v.z * w; acc.w += v.w * w;
    }
    red4[grp * 16 + q] = acc;
    __syncthreads();
    if (tid < 64) {
        const float* red = (const float*)red4;
        float tot = 0.0f;
        #pragma unroll
        for (int k = 0; k < 16; ++k) tot += red[k * 64 + tid];
        out[g * HIDDEN + tid] = tot * rz;
    }
}

extern "C" void kernel_launch(void* const* d_in, const int* in_sizes, int n_in,
                              void* d_out, int out_size) {
    const float* x      = (const float*)d_in[0];
    const void*  ei     = d_in[1];
    const void*  batch  = d_in[2];
    const float* W_rel  = (const float*)d_in[3];
    const float* b_rel  = (const float*)d_in[4];
    const float* W_root = (const float*)d_in[5];
    float*       out    = (float*)d_out;
    (void)in_sizes; (void)n_in; (void)out_size;

    k1_dots_bounds<<<DOTS_BLOCKS + BOUNDS_BLOCKS, 256>>>(
        x, W_rel, b_rel, W_root, batch, (const int*)ei);
    k_edges<<<(N_EDGES / EPT + 255) / 256, 256>>>(ei);
    k_pool<<<NUM_GRAPHS, 256>>>(x, out);
}

// round 7
// speedup vs baseline: 1.0458x; 1.0458x over previous
#include <cuda_runtime.h>
#include <cuda_bf16.h>
#include <math.h>

#define N_NODES    100000
#define N_EDGES    1600000
#define HIDDEN     64
#define NUM_GRAPHS 512

// Scratch (no allocations -> __device__ globals)
__device__ float g_p[N_NODES];            // x . W_rel
__device__ float g_score[N_NODES];        // x . W_root + b_rel + sum_edges p[src]
__device__ int   g_start[NUM_GRAPHS + 1]; // per-graph node range starts

// ---- inline dtype sniff: odd int32 words of edge buffer are all 0 iff int64 ----
__device__ __forceinline__ int sniff_is64(const int* __restrict__ ei32) {
    int a = ei32[1], b = ei32[3], c = ei32[5], d = ei32[7];  // L1-resident
    return ((a | b) | (c | d)) == 0;
}

__device__ __forceinline__ int load_idx(const void* p, long long i, int is64) {
    if (is64) return (int)((const long long*)p)[i];
    return ((const int*)p)[i];
}

// ---------- K1: fused node dots + graph bounds ----------
// Dots: 4 lanes per node, 8 nodes per warp.
//   - each LDG.128 is coalesced across 8 consecutive rows (8 lines/load)
//   - 4 independent loads per thread (MLP=4)
//   - reduction: 2 shuffle levels (width 4) x 2 values
#define NODES_PER_BLOCK 64
#define DOTS_BLOCKS   ((N_NODES + NODES_PER_BLOCK - 1) / NODES_PER_BLOCK)  // 1563
#define BOUNDS_BLOCKS ((N_NODES + 4 * 256 - 1) / (4 * 256))                // 98
__global__ __launch_bounds__(256)
void k1_dots_bounds(const float* __restrict__ x,
                    const float* __restrict__ W_rel,
                    const float* __restrict__ b_rel,
                    const float* __restrict__ W_root,
                    const void*  __restrict__ batch,
                    const int*   __restrict__ ei32) {
    if (blockIdx.x < DOTS_BLOCKS) {
        int t    = blockIdx.x * 256 + threadIdx.x;
        int warp = t >> 5;
        int lane = t & 31;
        int node = warp * 8 + (lane >> 2);
        int sub  = lane & 3;
        if (node >= N_NODES) return;

        const float4* row = (const float4*)(x + (size_t)node * HIDDEN);
        float sr = 0.0f, so = 0.0f;
        #pragma unroll
        for (int k = 0; k < 4; ++k) {
            float4 v = row[sub + 4 * k];                       // independent loads
            float4 a = __ldg((const float4*)W_rel  + sub + 4 * k);
            float4 c = __ldg((const float4*)W_root + sub + 4 * k);
            sr += v.x * a.x + v.y * a.y + v.z * a.z + v.w * a.w;
            so += v.x * c.x + v.y * c.y + v.z * c.z + v.w * c.w;
        }
        sr += __shfl_down_sync(0xFFFFFFFFu, sr, 2, 4);
        so += __shfl_down_sync(0xFFFFFFFFu, so, 2, 4);
        sr += __shfl_down_sync(0xFFFFFFFFu, sr, 1, 4);
        so += __shfl_down_sync(0xFFFFFFFFu, so, 1, 4);
        if (sub == 0) {
            g_p[node]     = sr;
            g_score[node] = so + __ldg(&b_rel[0]);
        }
    } else {
        // ---- graph bounds (batch is sorted) ----
        int is64 = sniff_is64(ei32);
        int t  = (blockIdx.x - DOTS_BLOCKS) * blockDim.x + threadIdx.x;
        int i0 = t * 4;
        if (i0 >= N_NODES) return;
        int b0, b1, b2, b3, prev;
        if (!is64 && i0 + 4 <= N_NODES) {
            int4 v = ((const int4*)batch)[t];
            b0 = v.x; b1 = v.y; b2 = v.z; b3 = v.w;
            prev = (i0 == 0) ? -1 : ((const int*)batch)[i0 - 1];
        } else {
            b0 = (i0     < N_NODES) ? load_idx(batch, i0,     is64) : -2;
            b1 = (i0 + 1 < N_NODES) ? load_idx(batch, i0 + 1, is64) : -2;
            b2 = (i0 + 2 < N_NODES) ? load_idx(batch, i0 + 2, is64) : -2;
            b3 = (i0 + 3 < N_NODES) ? load_idx(batch, i0 + 3, is64) : -2;
            prev = (i0 == 0) ? -1 : load_idx(batch, i0 - 1, is64);
        }
        int bs[4] = {b0, b1, b2, b3};
        #pragma unroll
        for (int j = 0; j < 4; ++j) {
            int i = i0 + j;
            if (i >= N_NODES) break;
            int b = bs[j];
            for (int g = prev + 1; g <= b; ++g) g_start[g] = i;
            if (i == N_NODES - 1)
                for (int g = b + 1; g <= NUM_GRAPHS; ++g) g_start[g] = N_NODES;
            prev = b;
        }
    }
}

// ---------- K2: edge scatter, 8 edges/thread (at L2 atomic sector floor) ----------
#define EPT 8
__global__ void k_edges(const void* __restrict__ edge_index) {
    int t  = blockIdx.x * blockDim.x + threadIdx.x;
    long long e0 = (long long)t * EPT;
    if (e0 >= N_EDGES) return;
    int is64 = sniff_is64((const int*)edge_index);
    if (!is64) {
        const int4* src4 = (const int4*)edge_index;
        const int4* dst4 = (const int4*)((const int*)edge_index + N_EDGES);
        int4 sa = src4[2 * t];
        int4 sb = src4[2 * t + 1];
        int4 da = dst4[2 * t];
        int4 db = dst4[2 * t + 1];
        float p0 = __ldg(&g_p[sa.x]);
        float p1 = __ldg(&g_p[sa.y]);
        float p2 = __ldg(&g_p[sa.z]);
        float p3 = __ldg(&g_p[sa.w]);
        float p4 = __ldg(&g_p[sb.x]);
        float p5 = __ldg(&g_p[sb.y]);
        float p6 = __ldg(&g_p[sb.z]);
        float p7 = __ldg(&g_p[sb.w]);
        atomicAdd(&g_score[da.x], p0);
        atomicAdd(&g_score[da.y], p1);
        atomicAdd(&g_score[da.z], p2);
        atomicAdd(&g_score[da.w], p3);
        atomicAdd(&g_score[db.x], p4);
        atomicAdd(&g_score[db.y], p5);
        atomicAdd(&g_score[db.z], p6);
        atomicAdd(&g_score[db.w], p7);
    } else {
        #pragma unroll
        for (int k = 0; k < EPT; ++k) {
            long long e = e0 + k;
            if (e < N_EDGES) {
                int s = load_idx(edge_index, e, 1);
                int d = load_idx(edge_index, (long long)N_EDGES + e, 1);
                atomicAdd(&g_score[d], g_p[s]);
            }
        }
    }
}

// ---------- K3: fused per-graph online softmax + weighted pooling ----------
__global__ __launch_bounds__(256, 4)
void k_pool(const float* __restrict__ x, float* __restrict__ out) {
    __shared__ float red_m[256];
    __shared__ float red_z[256];
    __shared__ float s_m, s_rz;
    __shared__ __align__(16) float4 red4[16 * 16];  // phase-C partials [16 groups][16 float4]
    int g   = blockIdx.x;
    int tid = threadIdx.x;
    int s   = g_start[g];
    int e   = g_start[g + 1];

    // Phase A: online (max, sum-exp) in one pass. -1e30 sentinel avoids inf-inf NaN.
    float m = -1e30f, z = 0.0f;
    for (int i = s + tid; i < e; i += 256) {
        float sc = g_score[i];
        float nm = fmaxf(m, sc);
        z = z * __expf(m - nm) + __expf(sc - nm);
        m = nm;
    }
    red_m[tid] = m; red_z[tid] = z;
    __syncthreads();
    #pragma unroll
    for (int off = 128; off > 0; off >>= 1) {
        if (tid < off) {
            float ma = red_m[tid],       za = red_z[tid];
            float mb = red_m[tid + off], zb = red_z[tid + off];
            float nm = fmaxf(ma, mb);
            red_m[tid] = nm;
            red_z[tid] = za * __expf(ma - nm) + zb * __expf(mb - nm);
        }
        __syncthreads();
    }
    if (tid == 0) {
        s_m  = red_m[0];
        s_rz = (e > s && red_z[0] > 0.0f) ? (1.0f / red_z[0]) : 0.0f;
    }
    __syncthreads();
    m = s_m;
    float rz = s_rz;

    // Phase C: 16 groups of 16 threads; group handles rows s+grp, s+grp+16, ...
    // Each thread owns one float4 chunk of the 64-wide row.
    int q   = tid & 15;         // float4 index within row
    int grp = tid >> 4;         // 16 groups
    float4 acc = make_float4(0.f, 0.f, 0.f, 0.f);
    const float4* x4 = (const float4*)x;
    for (int i = s + grp; i < e; i += 16) {
        float w = __expf(g_score[i] - m);    // broadcast within group
        float4 v = x4[(size_t)i * 16 + q];
        acc.x += v.x * w; acc.y += v.y * w; acc.z += v.z * w; acc.w += v.w * w;
    }
    red4[grp * 16 + q] = acc;
    __syncthreads();
    if (tid < 64) {
        const float* red = (const float*)red4;
        float tot = 0.0f;
        #pragma unroll
        for (int k = 0; k < 16; ++k) tot += red[k * 64 + tid];
        out[g * HIDDEN + tid] = tot * rz;
    }
}

extern "C" void kernel_launch(void* const* d_in, const int* in_sizes, int n_in,
                              void* d_out, int out_size) {
    const float* x      = (const float*)d_in[0];
    const void*  ei     = d_in[1];
    const void*  batch  = d_in[2];
    const float* W_rel  = (const float*)d_in[3];
    const float* b_rel  = (const float*)d_in[4];
    const float* W_root = (const float*)d_in[5];
    float*       out    = (float*)d_out;
    (void)in_sizes; (void)n_in; (void)out_size;

    k1_dots_bounds<<<DOTS_BLOCKS + BOUNDS_BLOCKS, 256>>>(
        x, W_rel, b_rel, W_root, batch, (const int*)ei);
    k_edges<<<(N_EDGES / EPT + 255) / 256, 256>>>(ei);
    k_pool<<<NUM_GRAPHS, 256>>>(x, out);
}

// round 8
// speedup vs baseline: 1.2207x; 1.1672x over previous
#include <cuda_runtime.h>
#include <cuda_bf16.h>
#include <math.h>

#define N_NODES    100000
#define N_EDGES    1600000
#define HIDDEN     64
#define NUM_GRAPHS 512

// Scratch (no allocations -> __device__ globals)
__device__ float g_p[N_NODES];            // x . W_rel
__device__ float g_score[N_NODES];        // x . W_root + b_rel + sum_edges p[src]
__device__ int   g_start[NUM_GRAPHS + 1]; // per-graph node range starts

// ---- inline dtype sniff: odd int32 words of edge buffer are all 0 iff int64 ----
__device__ __forceinline__ int sniff_is64(const int* __restrict__ ei32) {
    int a = ei32[1], b = ei32[3], c = ei32[5], d = ei32[7];  // L1-resident
    return ((a | b) | (c | d)) == 0;
}

__device__ __forceinline__ int load_idx(const void* p, long long i, int is64) {
    if (is64) return (int)((const long long*)p)[i];
    return ((const int*)p)[i];
}

// ---------- K1: fused node dots + graph bounds ----------
// Dots: 4 lanes per node-pair, 16 nodes per warp, 8 independent float4 loads/thread.
#define NODES_PER_BLOCK 128
#define DOTS_BLOCKS   ((N_NODES + NODES_PER_BLOCK - 1) / NODES_PER_BLOCK)  // 782
#define BOUNDS_BLOCKS ((N_NODES + 4 * 256 - 1) / (4 * 256))                // 98
__global__ __launch_bounds__(256)
void k1_dots_bounds(const float* __restrict__ x,
                    const float* __restrict__ W_rel,
                    const float* __restrict__ b_rel,
                    const float* __restrict__ W_root,
                    const void*  __restrict__ batch,
                    const int*   __restrict__ ei32) {
    if (blockIdx.x < DOTS_BLOCKS) {
        int t     = blockIdx.x * 256 + threadIdx.x;
        int warp  = t >> 5;
        int lane  = t & 31;
        int node0 = warp * 16 + (lane >> 2) * 2;   // this group's first node
        int sub   = lane & 3;
        if (node0 >= N_NODES) return;
        bool has1 = (node0 + 1 < N_NODES);

        const float4* row0 = (const float4*)(x + (size_t)node0 * HIDDEN);
        const float4* row1 = (const float4*)(x + (size_t)(node0 + (has1 ? 1 : 0)) * HIDDEN);

        // Issue all 8 loads up front (MLP=8)
        float4 v0[4], v1[4];
        #pragma unroll
        for (int k = 0; k < 4; ++k) v0[k] = row0[sub + 4 * k];
        #pragma unroll
        for (int k = 0; k < 4; ++k) v1[k] = row1[sub + 4 * k];

        float sr0 = 0.f, so0 = 0.f, sr1 = 0.f, so1 = 0.f;
        #pragma unroll
        for (int k = 0; k < 4; ++k) {
            float4 a = __ldg((const float4*)W_rel  + sub + 4 * k);
            float4 c = __ldg((const float4*)W_root + sub + 4 * k);
            sr0 += v0[k].x * a.x + v0[k].y * a.y + v0[k].z * a.z + v0[k].w * a.w;
            so0 += v0[k].x * c.x + v0[k].y * c.y + v0[k].z * c.z + v0[k].w * c.w;
            sr1 += v1[k].x * a.x + v1[k].y * a.y + v1[k].z * a.z + v1[k].w * a.w;
            so1 += v1[k].x * c.x + v1[k].y * c.y + v1[k].z * c.z + v1[k].w * c.w;
        }
        #pragma unroll
        for (int off = 2; off > 0; off >>= 1) {
            sr0 += __shfl_down_sync(0xFFFFFFFFu, sr0, off, 4);
            so0 += __shfl_down_sync(0xFFFFFFFFu, so0, off, 4);
            sr1 += __shfl_down_sync(0xFFFFFFFFu, sr1, off, 4);
            so1 += __shfl_down_sync(0xFFFFFFFFu, so1, off, 4);
        }
        if (sub == 0) {
            float bias = __ldg(&b_rel[0]);
            g_p[node0]     = sr0;
            g_score[node0] = so0 + bias;
            if (has1) {
                g_p[node0 + 1]     = sr1;
                g_score[node0 + 1] = so1 + bias;
            }
        }
    } else {
        // ---- graph bounds (batch is sorted) ----
        int is64 = sniff_is64(ei32);
        int t  = (blockIdx.x - DOTS_BLOCKS) * blockDim.x + threadIdx.x;
        int i0 = t * 4;
        if (i0 >= N_NODES) return;
        int b0, b1, b2, b3, prev;
        if (!is64 && i0 + 4 <= N_NODES) {
            int4 v = ((const int4*)batch)[t];
            b0 = v.x; b1 = v.y; b2 = v.z; b3 = v.w;
            prev = (i0 == 0) ? -1 : ((const int*)batch)[i0 - 1];
        } else {
            b0 = (i0     < N_NODES) ? load_idx(batch, i0,     is64) : -2;
            b1 = (i0 + 1 < N_NODES) ? load_idx(batch, i0 + 1, is64) : -2;
            b2 = (i0 + 2 < N_NODES) ? load_idx(batch, i0 + 2, is64) : -2;
            b3 = (i0 + 3 < N_NODES) ? load_idx(batch, i0 + 3, is64) : -2;
            prev = (i0 == 0) ? -1 : load_idx(batch, i0 - 1, is64);
        }
        int bs[4] = {b0, b1, b2, b3};
        #pragma unroll
        for (int j = 0; j < 4; ++j) {
            int i = i0 + j;
            if (i >= N_NODES) break;
            int b = bs[j];
            for (int g = prev + 1; g <= b; ++g) g_start[g] = i;
            if (i == N_NODES - 1)
                for (int g = b + 1; g <= NUM_GRAPHS; ++g) g_start[g] = N_NODES;
            prev = b;
        }
    }
}

// ---------- K2: edge scatter, 16 edges/thread ----------
#define EPT 16
__global__ void k_edges(const void* __restrict__ edge_index) {
    int t  = blockIdx.x * blockDim.x + threadIdx.x;
    long long e0 = (long long)t * EPT;
    if (e0 >= N_EDGES) return;
    int is64 = sniff_is64((const int*)edge_index);
    if (!is64) {
        const int4* src4 = (const int4*)edge_index;
        const int4* dst4 = (const int4*)((const int*)edge_index + N_EDGES);
        int4 s[4], d[4];
        #pragma unroll
        for (int k = 0; k < 4; ++k) s[k] = src4[4 * t + k];
        #pragma unroll
        for (int k = 0; k < 4; ++k) d[k] = dst4[4 * t + k];
        float p[16];
        #pragma unroll
        for (int k = 0; k < 4; ++k) {
            p[4 * k + 0] = __ldg(&g_p[s[k].x]);
            p[4 * k + 1] = __ldg(&g_p[s[k].y]);
            p[4 * k + 2] = __ldg(&g_p[s[k].z]);
            p[4 * k + 3] = __ldg(&g_p[s[k].w]);
        }
        #pragma unroll
        for (int k = 0; k < 4; ++k) {
            atomicAdd(&g_score[d[k].x], p[4 * k + 0]);
            atomicAdd(&g_score[d[k].y], p[4 * k + 1]);
            atomicAdd(&g_score[d[k].z], p[4 * k + 2]);
            atomicAdd(&g_score[d[k].w], p[4 * k + 3]);
        }
    } else {
        #pragma unroll
        for (int k = 0; k < EPT; ++k) {
            long long e = e0 + k;
            if (e < N_EDGES) {
                int s = load_idx(edge_index, e, 1);
                int d = load_idx(edge_index, (long long)N_EDGES + e, 1);
                atomicAdd(&g_score[d], g_p[s]);
            }
        }
    }
}

// ---------- K3: fused per-graph online softmax + weighted pooling ----------
__global__ __launch_bounds__(256, 4)
void k_pool(const float* __restrict__ x, float* __restrict__ out) {
    __shared__ float red_m[256];
    __shared__ float red_z[256];
    __shared__ float s_m, s_rz;
    __shared__ __align__(16) float4 red4[16 * 16];  // phase-C partials [16 groups][16 float4]
    int g   = blockIdx.x;
    int tid = threadIdx.x;
    int s   = g_start[g];
    int e   = g_start[g + 1];

    // Phase A: online (max, sum-exp) in one pass. -1e30 sentinel avoids inf-inf NaN.
    float m = -1e30f, z = 0.0f;
    for (int i = s + tid; i < e; i += 256) {
        float sc = g_score[i];
        float nm = fmaxf(m, sc);
        z = z * __expf(m - nm) + __expf(sc - nm);
        m = nm;
    }
    red_m[tid] = m; red_z[tid] = z;
    __syncthreads();
    #pragma unroll
    for (int off = 128; off > 0; off >>= 1) {
        if (tid < off) {
            float ma = red_m[tid],       za = red_z[tid];
            float mb = red_m[tid + off], zb = red_z[tid + off];
            float nm = fmaxf(ma, mb);
            red_m[tid] = nm;
            red_z[tid] = za * __expf(ma - nm) + zb * __expf(mb - nm);
        }
        __syncthreads();
    }
    if (tid == 0) {
        s_m  = red_m[0];
        s_rz = (e > s && red_z[0] > 0.0f) ? (1.0f / red_z[0]) : 0.0f;
    }
    __syncthreads();
    m = s_m;
    float rz = s_rz;

    // Phase C: 16 groups of 16 threads; group handles rows s+grp, s+grp+16, ...
    // Unrolled x2: two rows in flight per thread.
    int q   = tid & 15;         // float4 index within row
    int grp = tid >> 4;         // 16 groups
    float4 acc0 = make_float4(0.f, 0.f, 0.f, 0.f);
    float4 acc1 = make_float4(0.f, 0.f, 0.f, 0.f);
    const float4* x4 = (const float4*)x;
    int i = s + grp;
    for (; i + 16 < e; i += 32) {
        float  sc0 = g_score[i];
        float  sc1 = g_score[i + 16];
        float4 v0  = x4[(size_t)i * 16 + q];
        float4 v1  = x4[(size_t)(i + 16) * 16 + q];
        float  w0  = __expf(sc0 - m);
        float  w1  = __expf(sc1 - m);
        acc0.x += v0.x * w0; acc0.y += v0.y * w0; acc0.z += v0.z * w0; acc0.w += v0.w * w0;
        acc1.x += v1.x * w1; acc1.y += v1.y * w1; acc1.z += v1.z * w1; acc1.w += v1.w * w1;
    }
    if (i < e) {
        float  w = __expf(g_score[i] - m);
        float4 v = x4[(size_t)i * 16 + q];
        acc0.x += v.x * w; acc0.y += v.y * w; acc0.z += v.z * w; acc0.w += v.w * w;
    }
    acc0.x += acc1.x; acc0.y += acc1.y; acc0.z += acc1.z; acc0.w += acc1.w;
    red4[grp * 16 + q] = acc0;
    __syncthreads();
    if (tid < 64) {
        const float* red = (const float*)red4;
        float tot = 0.0f;
        #pragma unroll
        for (int k = 0; k < 16; ++k) tot += red[k * 64 + tid];
        out[g * HIDDEN + tid] = tot * rz;
    }
}

extern "C" void kernel_launch(void* const* d_in, const int* in_sizes, int n_in,
                              void* d_out, int out_size) {
    const float* x      = (const float*)d_in[0];
    const void*  ei     = d_in[1];
    const void*  batch  = d_in[2];
    const float* W_rel  = (const float*)d_in[3];
    const float* b_rel  = (const float*)d_in[4];
    const float* W_root = (const float*)d_in[5];
    float*       out    = (float*)d_out;
    (void)in_sizes; (void)n_in; (void)out_size;

    k1_dots_bounds<<<DOTS_BLOCKS + BOUNDS_BLOCKS, 256>>>(
        x, W_rel, b_rel, W_root, batch, (const int*)ei);
    k_edges<<<(N_EDGES / EPT + 255) / 256, 256>>>(ei);
    k_pool<<<NUM_GRAPHS, 256>>>(x, out);
}

// round 9
// speedup vs baseline: 1.2792x; 1.0479x over previous
#include <cuda_runtime.h>
#include <cuda_bf16.h>
#include <math.h>

#define N_NODES    100000
#define N_EDGES    1600000
#define HIDDEN     64
#define NUM_GRAPHS 512

// Scratch (no allocations -> __device__ globals)
__device__ float g_p[N_NODES];            // x . W_rel
__device__ float g_score[N_NODES];        // x . W_root + b_rel + sum_edges p[src]
__device__ int   g_start[NUM_GRAPHS + 1]; // per-graph node range starts

// ---- inline dtype sniff: odd int32 words of edge buffer are all 0 iff int64 ----
__device__ __forceinline__ int sniff_is64(const int* __restrict__ ei32) {
    int a = ei32[1], b = ei32[3], c = ei32[5], d = ei32[7];  // L1-resident
    return ((a | b) | (c | d)) == 0;
}

__device__ __forceinline__ int load_idx(const void* p, long long i, int is64) {
    if (is64) return (int)((const long long*)p)[i];
    return ((const int*)p)[i];
}

// ---------- K1: fused node dots + graph bounds ----------
// Dots: 8 lanes per row-half -> every LDG.128 covers 4 FULL 128B lines.
// Warp = 4 groups x 8 lanes; group j handles nodes base+j+4k, k=0..3.
// 8 independent float4 loads per thread (MLP=8), W held in registers.
#define NODES_PER_BLOCK 128
#define DOTS_BLOCKS   ((N_NODES + NODES_PER_BLOCK - 1) / NODES_PER_BLOCK)  // 782
#define BOUNDS_BLOCKS ((N_NODES + 4 * 256 - 1) / (4 * 256))                // 98
__global__ __launch_bounds__(256)
void k1_dots_bounds(const float* __restrict__ x,
                    const float* __restrict__ W_rel,
                    const float* __restrict__ b_rel,
                    const float* __restrict__ W_root,
                    const void*  __restrict__ batch,
                    const int*   __restrict__ ei32) {
    if (blockIdx.x < DOTS_BLOCKS) {
        int t    = blockIdx.x * 256 + threadIdx.x;
        int warp = t >> 5;
        int lane = t & 31;
        int j    = lane >> 3;          // group 0..3
        int q    = lane & 7;           // lane in group
        int base = warp * 16;          // 16 nodes per warp
        if (base >= N_NODES) return;

        float4 wr0 = __ldg((const float4*)W_rel  + q);
        float4 wr1 = __ldg((const float4*)W_rel  + 8 + q);
        float4 wo0 = __ldg((const float4*)W_root + q);
        float4 wo1 = __ldg((const float4*)W_root + 8 + q);

        float4 v0[4], v1[4];
        #pragma unroll
        for (int k = 0; k < 4; ++k) {
            int n = base + j + 4 * k;
            n = (n < N_NODES) ? n : (N_NODES - 1);
            const float4* row = (const float4*)(x + (size_t)n * HIDDEN);
            v0[k] = row[q];        // line 0 of this row
            v1[k] = row[8 + q];    // line 1 of this row
        }
        float sr[4], so[4];
        #pragma unroll
        for (int k = 0; k < 4; ++k) {
            sr[k] = v0[k].x * wr0.x + v0[k].y * wr0.y + v0[k].z * wr0.z + v0[k].w * wr0.w
                  + v1[k].x * wr1.x + v1[k].y * wr1.y + v1[k].z * wr1.z + v1[k].w * wr1.w;
            so[k] = v0[k].x * wo0.x + v0[k].y * wo0.y + v0[k].z * wo0.z + v0[k].w * wo0.w
                  + v1[k].x * wo1.x + v1[k].y * wo1.y + v1[k].z * wo1.z + v1[k].w * wo1.w;
        }
        #pragma unroll
        for (int off = 4; off > 0; off >>= 1) {
            #pragma unroll
            for (int k = 0; k < 4; ++k) {
                sr[k] += __shfl_down_sync(0xFFFFFFFFu, sr[k], off, 8);
                so[k] += __shfl_down_sync(0xFFFFFFFFu, so[k], off, 8);
            }
        }
        if (q == 0) {
            float bias = __ldg(&b_rel[0]);
            #pragma unroll
            for (int k = 0; k < 4; ++k) {
                int n = base + j + 4 * k;
                if (n < N_NODES) {
                    g_p[n]     = sr[k];
                    g_score[n] = so[k] + bias;
                }
            }
        }
    } else {
        // ---- graph bounds (batch is sorted) ----
        int is64 = sniff_is64(ei32);
        int t  = (blockIdx.x - DOTS_BLOCKS) * blockDim.x + threadIdx.x;
        int i0 = t * 4;
        if (i0 >= N_NODES) return;
        int b0, b1, b2, b3, prev;
        if (!is64 && i0 + 4 <= N_NODES) {
            int4 v = ((const int4*)batch)[t];
            b0 = v.x; b1 = v.y; b2 = v.z; b3 = v.w;
            prev = (i0 == 0) ? -1 : ((const int*)batch)[i0 - 1];
        } else {
            b0 = (i0     < N_NODES) ? load_idx(batch, i0,     is64) : -2;
            b1 = (i0 + 1 < N_NODES) ? load_idx(batch, i0 + 1, is64) : -2;
            b2 = (i0 + 2 < N_NODES) ? load_idx(batch, i0 + 2, is64) : -2;
            b3 = (i0 + 3 < N_NODES) ? load_idx(batch, i0 + 3, is64) : -2;
            prev = (i0 == 0) ? -1 : load_idx(batch, i0 - 1, is64);
        }
        int bs[4] = {b0, b1, b2, b3};
        #pragma unroll
        for (int j = 0; j < 4; ++j) {
            int i = i0 + j;
            if (i >= N_NODES) break;
            int b = bs[j];
            for (int g = prev + 1; g <= b; ++g) g_start[g] = i;
            if (i == N_NODES - 1)
                for (int g = b + 1; g <= NUM_GRAPHS; ++g) g_start[g] = N_NODES;
            prev = b;
        }
    }
}

// ---------- K2: edge scatter, 16 edges/thread, PDL ----------
// Index loads (input buffer, 12.8MB DRAM) issue BEFORE the grid-dependency
// sync -> they overlap k1's execution. Gathers/atomics (touch g_p/g_score)
// happen after the sync.
#define EPT 16
__global__ void k_edges(const void* __restrict__ edge_index) {
    int t  = blockIdx.x * blockDim.x + threadIdx.x;
    long long e0 = (long long)t * EPT;
    if (e0 >= N_EDGES) {
#if __CUDA_ARCH__ >= 900
        cudaGridDependencySynchronize();
#endif
        return;
    }
    int is64 = sniff_is64((const int*)edge_index);
    if (!is64) {
        const int4* src4 = (const int4*)edge_index;
        const int4* dst4 = (const int4*)((const int*)edge_index + N_EDGES);
        int4 s[4], d[4];
        #pragma unroll
        for (int k = 0; k < 4; ++k) s[k] = src4[4 * t + k];
        #pragma unroll
        for (int k = 0; k < 4; ++k) d[k] = dst4[4 * t + k];
#if __CUDA_ARCH__ >= 900
        cudaGridDependencySynchronize();
#endif
        float p[16];
        #pragma unroll
        for (int k = 0; k < 4; ++k) {
            p[4 * k + 0] = __ldg(&g_p[s[k].x]);
            p[4 * k + 1] = __ldg(&g_p[s[k].y]);
            p[4 * k + 2] = __ldg(&g_p[s[k].z]);
            p[4 * k + 3] = __ldg(&g_p[s[k].w]);
        }
        #pragma unroll
        for (int k = 0; k < 4; ++k) {
            atomicAdd(&g_score[d[k].x], p[4 * k + 0]);
            atomicAdd(&g_score[d[k].y], p[4 * k + 1]);
            atomicAdd(&g_score[d[k].z], p[4 * k + 2]);
            atomicAdd(&g_score[d[k].w], p[4 * k + 3]);
        }
    } else {
        int sIdx[EPT], dIdx[EPT];
        #pragma unroll
        for (int k = 0; k < EPT; ++k) {
            long long e = e0 + k;
            sIdx[k] = (e < N_EDGES) ? load_idx(edge_index, e, 1) : 0;
            dIdx[k] = (e < N_EDGES) ? load_idx(edge_index, (long long)N_EDGES + e, 1) : -1;
        }
#if __CUDA_ARCH__ >= 900
        cudaGridDependencySynchronize();
#endif
        #pragma unroll
        for (int k = 0; k < EPT; ++k)
            if (dIdx[k] >= 0) atomicAdd(&g_score[dIdx[k]], g_p[sIdx[k]]);
    }
}

// ---------- K3: fused per-graph online softmax + weighted pooling (PDL) ----------
__global__ __launch_bounds__(256, 4)
void k_pool(const float* __restrict__ x, float* __restrict__ out) {
    __shared__ float red_m[256];
    __shared__ float red_z[256];
    __shared__ float s_m, s_rz;
    __shared__ __align__(16) float4 red4[16 * 16];  // phase-C partials
#if __CUDA_ARCH__ >= 900
    cudaGridDependencySynchronize();   // overlap launch with k_edges tail
#endif
    int g   = blockIdx.x;
    int tid = threadIdx.x;
    int s   = g_start[g];
    int e   = g_start[g + 1];

    // Phase A: online (max, sum-exp) in one pass.
    float m = -1e30f, z = 0.0f;
    for (int i = s + tid; i < e; i += 256) {
        float sc = g_score[i];
        float nm = fmaxf(m, sc);
        z = z * __expf(m - nm) + __expf(sc - nm);
        m = nm;
    }
    red_m[tid] = m; red_z[tid] = z;
    __syncthreads();
    #pragma unroll
    for (int off = 128; off > 0; off >>= 1) {
        if (tid < off) {
            float ma = red_m[tid],       za = red_z[tid];
            float mb = red_m[tid + off], zb = red_z[tid + off];
            float nm = fmaxf(ma, mb);
            red_m[tid] = nm;
            red_z[tid] = za * __expf(ma - nm) + zb * __expf(mb - nm);
        }
        __syncthreads();
    }
    if (tid == 0) {
        s_m  = red_m[0];
        s_rz = (e > s && red_z[0] > 0.0f) ? (1.0f / red_z[0]) : 0.0f;
    }
    __syncthreads();
    m = s_m;
    float rz = s_rz;

    // Phase C: 16 groups x 16 threads, 2 rows in flight per thread.
    int q   = tid & 15;
    int grp = tid >> 4;
    float4 acc0 = make_float4(0.f, 0.f, 0.f, 0.f);
    float4 acc1 = make_float4(0.f, 0.f, 0.f, 0.f);
    const float4* x4 = (const float4*)x;
    int i = s + grp;
    for (; i + 16 < e; i += 32) {
        float  sc0 = g_score[i];
        float  sc1 = g_score[i + 16];
        float4 v0  = x4[(size_t)i * 16 + q];
        float4 v1  = x4[(size_t)(i + 16) * 16 + q];
        float  w0  = __expf(sc0 - m);
        float  w1  = __expf(sc1 - m);
        acc0.x += v0.x * w0; acc0.y += v0.y * w0; acc0.z += v0.z * w0; acc0.w += v0.w * w0;
        acc1.x += v1.x * w1; acc1.y += v1.y * w1; acc1.z += v1.z * w1; acc1.w += v1.w * w1;
    }
    if (i < e) {
        float  w = __expf(g_score[i] - m);
        float4 v = x4[(size_t)i * 16 + q];
        acc0.x += v.x * w; acc0.y += v.y * w; acc0.z += v.z * w; acc0.w += v.w * w;
    }
    acc0.x += acc1.x; acc0.y += acc1.y; acc0.z += acc1.z; acc0.w += acc1.w;
    red4[grp * 16 + q] = acc0;
    __syncthreads();
    if (tid < 64) {
        const float* red = (const float*)red4;
        float tot = 0.0f;
        #pragma unroll
        for (int k = 0; k < 16; ++k) tot += red[k * 64 + tid];
        out[g * HIDDEN + tid] = tot * rz;
    }
}

extern "C" void kernel_launch(void* const* d_in, const int* in_sizes, int n_in,
                              void* d_out, int out_size) {
    const float* x      = (const float*)d_in[0];
    const void*  ei     = d_in[1];
    const void*  batch  = d_in[2];
    const float* W_rel  = (const float*)d_in[3];
    const float* b_rel  = (const float*)d_in[4];
    const float* W_root = (const float*)d_in[5];
    float*       out    = (float*)d_out;
    (void)in_sizes; (void)n_in; (void)out_size;

    // K1: plain launch (first in chain)
    k1_dots_bounds<<<DOTS_BLOCKS + BOUNDS_BLOCKS, 256>>>(
        x, W_rel, b_rel, W_root, batch, (const int*)ei);

    // K2 + K3: PDL so pre-sync work (edge-index DRAM reads, launch setup)
    // overlaps the predecessor kernel.
    cudaLaunchAttribute pdl[1];
    pdl[0].id = cudaLaunchAttributeProgrammaticStreamSerialization;
    pdl[0].val.programmaticStreamSerializationAllowed = 1;

    {
        cudaLaunchConfig_t cfg = {};
        cfg.gridDim  = dim3((N_EDGES / EPT + 255) / 256);
        cfg.blockDim = dim3(256);
        cfg.stream   = 0;
        cfg.attrs    = pdl;
        cfg.numAttrs = 1;
        cudaLaunchKernelEx(&cfg, k_edges, ei);
    }
    {
        cudaLaunchConfig_t cfg = {};
        cfg.gridDim  = dim3(NUM_GRAPHS);
        cfg.blockDim = dim3(256);
        cfg.stream   = 0;
        cfg.attrs    = pdl;
        cfg.numAttrs = 1;
        cudaLaunchKernelEx(&cfg, k_pool, x, out);
    }
}